// round 8
// baseline (speedup 1.0000x reference)
#include <cuda_runtime.h>
#include <cuda_fp16.h>
#include <math.h>
#include <stdint.h>

// ---------------- scratch (device globals: allocation-free contract) ----------------
__device__ __half g_h1[256 * 400 * 256];            // conv1 out [b][y][x][ci] fp16
__device__ __half g_wt[20736 * 256];                // conv2 W   [k = (ky*9+kx)*256+ci][co] fp16
__device__ float g_h2[256 * 9216];                  // conv2 out [b][pos][co]
__device__ float g_u[256 * 9216];                   // squashed  [b][co*36+pos]
__device__ __half g_uhat[(size_t)256 * 1152 * 160]; // u_hat     [b][i][o][d] fp16
__device__ float g_masked[256 * 160];
__device__ float g_d1[256 * 512];
__device__ float g_d2[256 * 1024];

__device__ __forceinline__ void mma_f16(float* c, const uint32_t* a, const uint32_t* b) {
    asm volatile(
        "mma.sync.aligned.m16n8k16.row.col.f32.f16.f16.f32 "
        "{%0,%1,%2,%3}, {%4,%5,%6,%7}, {%8,%9}, {%0,%1,%2,%3};"
        : "+f"(c[0]), "+f"(c[1]), "+f"(c[2]), "+f"(c[3])
        : "r"(a[0]), "r"(a[1]), "r"(a[2]), "r"(a[3]), "r"(b[0]), "r"(b[1]));
}
__device__ __forceinline__ void ldsm4(uint32_t* r, uint32_t addr) {
    asm volatile("ldmatrix.sync.aligned.m8n8.x4.shared.b16 {%0,%1,%2,%3}, [%4];"
        : "=r"(r[0]), "=r"(r[1]), "=r"(r[2]), "=r"(r[3]) : "r"(addr));
}
__device__ __forceinline__ void ldsm4t(uint32_t* r, uint32_t addr) {
    asm volatile("ldmatrix.sync.aligned.m8n8.x4.trans.shared.b16 {%0,%1,%2,%3}, [%4];"
        : "=r"(r[0]), "=r"(r[1]), "=r"(r[2]), "=r"(r[3]) : "r"(addr));
}
__device__ __forceinline__ void cp16(uint32_t smem_dst, const void* gsrc) {
    asm volatile("cp.async.cg.shared.global [%0], [%1], 16;" :: "r"(smem_dst), "l"(gsrc));
}
#define CP_COMMIT() asm volatile("cp.async.commit_group;")
#define CP_WAIT2()  asm volatile("cp.async.wait_group 2;")

// ---------------- conv1: [256,1,28,28] -> [b][y][x][co] channel-last fp16 ----------------
__global__ __launch_bounds__(128) void conv1_kernel(
    const float* __restrict__ x, const float* __restrict__ w,
    const float* __restrict__ bias) {
    __shared__ float xs[784];
    __shared__ float ws[128 * 81];
    int b = blockIdx.x;
    int cb = blockIdx.y * 128;
    int t = threadIdx.x;

    for (int idx = t; idx < 784; idx += 128) xs[idx] = x[b * 784 + idx];
    for (int idx = t; idx < 128 * 81; idx += 128) ws[idx] = w[cb * 81 + idx];
    __syncthreads();

    int co = cb + t;
    float bv = bias[co];
    __half* outp = g_h1 + (size_t)b * 400 * 256 + co;

    for (int oy = 0; oy < 20; oy++) {
        float acc[20];
#pragma unroll
        for (int j = 0; j < 20; j++) acc[j] = bv;
        for (int ky = 0; ky < 9; ky++) {
            float xr[28];
#pragma unroll
            for (int j = 0; j < 28; j++) xr[j] = xs[(oy + ky) * 28 + j];
#pragma unroll
            for (int kx = 0; kx < 9; kx++) {
                float wv = ws[t * 81 + ky * 9 + kx];
#pragma unroll
                for (int ox = 0; ox < 20; ox++) acc[ox] += wv * xr[ox + kx];
            }
        }
#pragma unroll
        for (int ox = 0; ox < 20; ox++)
            outp[(oy * 20 + ox) * 256] = __float2half_rn(acc[ox]);
    }
}

// ---------------- conv2 weight transpose -> fp16 [k][co] (co contiguous) ----------------
// tile: 32 co x (8 ci x 81 j); smem padded row 649 for conflict-free strided reads
__global__ void wtrans_kernel(const float* __restrict__ Wc) {
    extern __shared__ float s[];  // [32][649]
    int t = threadIdx.x;
    int ci0 = (blockIdx.x & 31) * 8;
    int co0 = (blockIdx.x >> 5) * 32;
    for (int idx = t; idx < 32 * 648; idx += 256) {
        int r = idx / 648, cch = idx - r * 648;
        s[r * 649 + cch] = Wc[(size_t)(co0 + r) * 20736 + ci0 * 81 + cch];
    }
    __syncthreads();
    for (int w = t; w < 648 * 32; w += 256) {
        int e = w >> 5, cop = w & 31;
        int cip = e / 81, j = e - cip * 81;
        g_wt[(size_t)(j * 256 + ci0 + cip) * 256 + co0 + cop] =
            __float2half_rn(s[cop * 649 + e]);
    }
}

// ---------------- conv2: fp16 mma m16n8k16, ldmatrix, 4-stage cp.async ----------------
// D'[pos(128) x co(128)] = H[pos][k] * W[k][co]; K = 81*256, k-tile 64.
#define LDA_H 72                       // A row: 64 halfs + 8 pad (144B)
#define LDB_H 136                      // B row: 128 halfs + 8 pad (272B)
#define A_ST (128 * LDA_H)             // 9216 halfs / stage
#define B_ST (64 * LDB_H)              // 8704 halfs / stage
#define SM_DYN (4 * (A_ST + B_ST) * 2) // 143360 bytes

__global__ __launch_bounds__(256) void conv2_mma(const float* __restrict__ bias) {
    extern __shared__ __half smemh[];
    __half* Abuf = smemh;                // [4][128][LDA_H]  (H tile: rows = pos)
    __half* Bbuf = smemh + 4 * A_ST;     // [4][64][LDB_H]   (W tile: rows = k)
    __shared__ int nOffT[128];
    __shared__ int o2Off[128];

    int t = threadIdx.x;
    int bx = blockIdx.x, by = blockIdx.y;
    int wid = t >> 5, lane = t & 31;
    int g = lane >> 2, tg = lane & 3;
    int warp_m = wid >> 2, warp_n = wid & 3;   // m over pos (2), n over co (4)

    if (t < 128) {
        int n = bx * 128 + t;
        int b = n / 36, pos = n - b * 36;
        int oy = pos / 6, ox = pos - oy * 6;
        nOffT[t] = (b * 400 + oy * 40 + ox * 2) * 256;
        o2Off[t] = (b * 36 + pos) * 256;
    }
    __syncthreads();

    // loader roles
    int arow = t >> 3, aseg = (t & 7) * 8;     // A: 128 rows x 8 segs (16B)
    int brow = t >> 4, bseg = (t & 15) * 8;    // B: 64 rows x 16 segs
    const __half* wbase = g_wt + by * 128;

    const int ITERS = 324;  // 81 * 4

    auto issue = [&](int ii) {
        int s = ii & 3;
        int kxy = ii >> 2, cib = (ii & 3) << 6;
        int ky = kxy / 9, kx = kxy - ky * 9;
        int hoff = (ky * 20 + kx) * 256 + cib;
        __half* As_s = Abuf + s * A_ST;
        __half* Bs_s = Bbuf + s * B_ST;
#pragma unroll
        for (int q = 0; q < 4; q++) {
            int ar = arow + 32 * q;
            uint32_t da = (uint32_t)__cvta_generic_to_shared(As_s + ar * LDA_H + aseg);
            cp16(da, g_h1 + nOffT[ar] + hoff + aseg);
            int br = brow + 16 * q;
            uint32_t db = (uint32_t)__cvta_generic_to_shared(Bs_s + br * LDB_H + bseg);
            cp16(db, wbase + (size_t)(kxy * 256 + cib + br) * 256 + bseg);
        }
        CP_COMMIT();
    };

    issue(0); issue(1); issue(2);

    // fragment address bases (byte offsets in shared space)
    uint32_t a_base0 = (uint32_t)__cvta_generic_to_shared(Abuf) +
        ((warp_m * 64 + (lane & 15)) * LDA_H + (lane >> 4) * 8) * 2;
    int bj = lane >> 3, brr = lane & 7;
    uint32_t b_base0 = (uint32_t)__cvta_generic_to_shared(Bbuf) +
        (((bj & 1) * 8 + brr) * LDB_H + warp_n * 32 + (bj >> 1) * 8) * 2;

    float acc[4][4][4];
#pragma unroll
    for (int mi = 0; mi < 4; mi++)
#pragma unroll
        for (int ni = 0; ni < 4; ni++)
#pragma unroll
            for (int r = 0; r < 4; r++) acc[mi][ni][r] = 0.f;

    for (int i = 0; i < ITERS; i++) {
        CP_WAIT2();
        __syncthreads();
        if (i + 3 < ITERS) issue(i + 3);
        else CP_COMMIT();

        uint32_t aB = a_base0 + (uint32_t)(i & 3) * (A_ST * 2);
        uint32_t bB = b_base0 + (uint32_t)(i & 3) * (B_ST * 2);
#pragma unroll
        for (int ks = 0; ks < 4; ks++) {
            uint32_t a_f[4][4], b_f[2][4];
#pragma unroll
            for (int mi = 0; mi < 4; mi++)
                ldsm4(a_f[mi], aB + (mi * 16 * LDA_H + ks * 16) * 2);
#pragma unroll
            for (int pr = 0; pr < 2; pr++)
                ldsm4t(b_f[pr], bB + (ks * 16 * LDB_H + pr * 16) * 2);
#pragma unroll
            for (int mi = 0; mi < 4; mi++) {
                mma_f16(acc[mi][0], a_f[mi], &b_f[0][0]);
                mma_f16(acc[mi][1], a_f[mi], &b_f[0][2]);
                mma_f16(acc[mi][2], a_f[mi], &b_f[1][0]);
                mma_f16(acc[mi][3], a_f[mi], &b_f[1][2]);
            }
        }
    }

    // epilogue: rows = pos, cols = co; float2 stores
#pragma unroll
    for (int mi = 0; mi < 4; mi++) {
        int p0 = warp_m * 64 + mi * 16 + g;
        int o0 = o2Off[p0], o1 = o2Off[p0 + 8];
#pragma unroll
        for (int ni = 0; ni < 4; ni++) {
            int co = by * 128 + warp_n * 32 + ni * 8 + 2 * tg;
            float2 bv = *(const float2*)&bias[co];
            float2 v0 = make_float2(acc[mi][ni][0] + bv.x, acc[mi][ni][1] + bv.y);
            float2 v1 = make_float2(acc[mi][ni][2] + bv.x, acc[mi][ni][3] + bv.y);
            *(float2*)&g_h2[o0 + co] = v0;
            *(float2*)&g_h2[o1 + co] = v1;
        }
    }
}

// ---------------- squash over last spatial axis ----------------
__global__ void squash_conv_kernel() {
    int gid = blockIdx.x * blockDim.x + threadIdx.x;  // 393216
    int b = gid / 1536;
    int rem = gid - b * 1536;
    int oy = rem >> 8;
    int co = rem & 255;
    float v[6];
    float n2 = 0.f;
#pragma unroll
    for (int j = 0; j < 6; j++) {
        v[j] = g_h2[(size_t)(b * 36 + oy * 6 + j) * 256 + co];
        n2 += v[j] * v[j];
    }
    float nrm = sqrtf(n2);
    float sc = (n2 / (1.f + n2)) / (nrm + 1e-7f);
    float* q = g_u + (size_t)b * 9216 + co * 36 + oy * 6;
#pragma unroll
    for (int j = 0; j < 6; j++) q[j] = v[j] * sc;
}

// ---------------- u_hat (fp16 out): block = input capsule i ----------------
__global__ __launch_bounds__(320) void uhat_kernel2(const float* __restrict__ Wc) {
    __shared__ float u_s[2048];
    int i = blockIdx.x;
    int t = threadIdx.x;
    int b2 = t / 40;
    int od4 = t - b2 * 40;

    for (int idx = t; idx < 2048; idx += 320) {
        int b = idx >> 3, e = idx & 7;
        u_s[idx] = g_u[(size_t)b * 9216 + i * 8 + e];
    }
    int od0 = od4 * 4;
    int o = od0 >> 4;
    int d0 = od0 & 15;
    const float* wp = Wc + ((size_t)(o * 1152 + i) * 16 + d0) * 8;
    float w[4][8];
#pragma unroll
    for (int q = 0; q < 4; q++) {
        float4 w0 = *(const float4*)(wp + q * 8);
        float4 w1 = *(const float4*)(wp + q * 8 + 4);
        w[q][0] = w0.x; w[q][1] = w0.y; w[q][2] = w0.z; w[q][3] = w0.w;
        w[q][4] = w1.x; w[q][5] = w1.y; w[q][6] = w1.z; w[q][7] = w1.w;
    }
    __syncthreads();
    for (int bo = 0; bo < 32; bo++) {
        int b = bo * 8 + b2;
        float ue[8];
#pragma unroll
        for (int e = 0; e < 8; e++) ue[e] = u_s[b * 8 + e];
        float acc[4];
#pragma unroll
        for (int q = 0; q < 4; q++) {
            float a = 0.f;
#pragma unroll
            for (int e = 0; e < 8; e++) a += w[q][e] * ue[e];
            acc[q] = a;
        }
        __half2 h0 = __floats2half2_rn(acc[0], acc[1]);
        __half2 h1 = __floats2half2_rn(acc[2], acc[3]);
        __half2* dst = (__half2*)(g_uhat + ((size_t)b * 1152 + i) * 160 + od0);
        dst[0] = h0; dst[1] = h1;
    }
}

// ---------------- dynamic routing (3 iters fused), fp16 u_hat ----------------
__device__ __forceinline__ void route_accum(
    const float uh[5], const float* v0s, const float* v1s,
    int p, int lane, float sacc[5]) {
    float c[5];
    float lg[5];
#pragma unroll
    for (int og = 0; og < 5; og++) {
        float tsum = uh[og] * v0s[og * 32 + lane];
        if (p == 2) tsum += uh[og] * v1s[og * 32 + lane];
        tsum += __shfl_xor_sync(0xffffffffu, tsum, 8);
        tsum += __shfl_xor_sync(0xffffffffu, tsum, 4);
        tsum += __shfl_xor_sync(0xffffffffu, tsum, 2);
        tsum += __shfl_xor_sync(0xffffffffu, tsum, 1);
        lg[og] = tsum;
    }
    float m = lg[0];
#pragma unroll
    for (int og = 1; og < 5; og++) m = fmaxf(m, lg[og]);
    m = fmaxf(m, __shfl_xor_sync(0xffffffffu, m, 16));
    float ssum = 0.f;
#pragma unroll
    for (int og = 0; og < 5; og++) { c[og] = expf(lg[og] - m); ssum += c[og]; }
    ssum += __shfl_xor_sync(0xffffffffu, ssum, 16);
    float inv = 1.f / ssum;
#pragma unroll
    for (int og = 0; og < 5; og++) sacc[og] += (c[og] * inv) * uh[og];
}

__global__ __launch_bounds__(256) void routing_kernel(float* __restrict__ out_len) {
    int b = blockIdx.x;
    int tid = threadIdx.x;
    int lane = tid & 31, warp = tid >> 5;

    __shared__ float v0s[160], v1s[160], v2s[160];
    __shared__ float spart[8 * 160];
    __shared__ float sred[160];
    __shared__ float scale_s[10], len_s[10];
    __shared__ int amax_s;

    const __half* base = g_uhat + (size_t)b * 184320;

    for (int p = 0; p < 3; p++) {
        float sacc[5] = {0.f, 0.f, 0.f, 0.f, 0.f};
        for (int ii = warp; ii < 1152; ii += 16) {
            const __half* pA = base + ii * 160;
            const __half* pB = base + (ii + 8) * 160;
            float uhA[5], uhB[5];
#pragma unroll
            for (int og = 0; og < 5; og++) uhA[og] = __half2float(pA[og * 32 + lane]);
#pragma unroll
            for (int og = 0; og < 5; og++) uhB[og] = __half2float(pB[og * 32 + lane]);
            if (p == 0) {
#pragma unroll
                for (int og = 0; og < 5; og++) sacc[og] += 0.1f * (uhA[og] + uhB[og]);
            } else {
                route_accum(uhA, v0s, v1s, p, lane, sacc);
                route_accum(uhB, v0s, v1s, p, lane, sacc);
            }
        }
#pragma unroll
        for (int og = 0; og < 5; og++) spart[warp * 160 + og * 32 + lane] = sacc[og];
        __syncthreads();
        if (tid < 160) {
            float tot = 0.f;
#pragma unroll
            for (int w = 0; w < 8; w++) tot += spart[w * 160 + tid];
            sred[tid] = tot;
        }
        __syncthreads();
        if (tid < 10) {
            float n2 = 0.f;
#pragma unroll
            for (int d = 0; d < 16; d++) { float xv = sred[tid * 16 + d]; n2 += xv * xv; }
            float nrm = sqrtf(n2);
            scale_s[tid] = (n2 / (1.f + n2)) / (nrm + 1e-7f);
            if (p == 2) len_s[tid] = (n2 / (1.f + n2)) * (nrm / (nrm + 1e-7f));
        }
        __syncthreads();
        float* vdst = (p == 0) ? v0s : ((p == 1) ? v1s : v2s);
        if (tid < 160) vdst[tid] = sred[tid] * scale_s[tid >> 4];
        __syncthreads();
    }

    if (tid == 0) {
        int bi = 0;
        float best = len_s[0];
#pragma unroll
        for (int o = 1; o < 10; o++)
            if (len_s[o] > best) { best = len_s[o]; bi = o; }
        amax_s = bi;
    }
    if (tid < 10) out_len[b * 10 + tid] = len_s[tid];
    __syncthreads();
    if (tid < 160) g_masked[b * 160 + tid] = ((tid >> 4) == amax_s) ? v2s[tid] : 0.f;
}

// ---------------- decoder GEMM (64x64x16 tile, 4x4 micro), epilogue fused ----------------
template <int EPI>
__global__ __launch_bounds__(256) void gemm_epi(
    const float* __restrict__ A, const float* __restrict__ W,
    const float* __restrict__ bias, float* __restrict__ C,
    int M, int N, int K) {
    __shared__ float As[16][64];
    __shared__ float Bs[16][64];
    int t = threadIdx.x;
    int bx = blockIdx.x, by = blockIdx.y;
    int arow = t >> 2, ak = (t & 3) * 4;
    int bkr = t >> 4, bnc = (t & 15) * 4;
    int tx = t & 15, ty = t >> 4;

    float acc[4][4];
#pragma unroll
    for (int i = 0; i < 4; i++)
#pragma unroll
        for (int j = 0; j < 4; j++) acc[i][j] = 0.f;

    for (int kk = 0; kk < K; kk += 16) {
        float4 av = *(const float4*)(A + (size_t)(by * 64 + arow) * K + kk + ak);
        int n0 = bx * 64 + bnc;
        float4 bv = make_float4(0.f, 0.f, 0.f, 0.f);
        if (n0 < N) bv = *(const float4*)(W + (size_t)(kk + bkr) * N + n0);
        As[ak + 0][arow] = av.x; As[ak + 1][arow] = av.y;
        As[ak + 2][arow] = av.z; As[ak + 3][arow] = av.w;
        *(float4*)&Bs[bkr][bnc] = bv;
        __syncthreads();
#pragma unroll
        for (int kr = 0; kr < 16; kr++) {
            float af[4], bf[4];
            *(float4*)af = *(const float4*)&As[kr][ty * 4];
            *(float4*)bf = *(const float4*)&Bs[kr][tx * 4];
#pragma unroll
            for (int mi = 0; mi < 4; mi++)
#pragma unroll
                for (int ni = 0; ni < 4; ni++) acc[mi][ni] += af[mi] * bf[ni];
        }
        __syncthreads();
    }

#pragma unroll
    for (int mi = 0; mi < 4; mi++) {
        int m = by * 64 + ty * 4 + mi;
#pragma unroll
        for (int ni = 0; ni < 4; ni++) {
            int n = bx * 64 + tx * 4 + ni;
            if (n < N) {
                float v = acc[mi][ni] + bias[n];
                if (EPI == 1) v = fmaxf(v, 0.f);
                if (EPI == 2) v = 1.f / (1.f + expf(-v));
                C[(size_t)m * N + n] = v;
            }
        }
    }
}

// ---------------- launch ----------------
extern "C" void kernel_launch(void* const* d_in, const int* in_sizes, int n_in,
                              void* d_out, int out_size) {
    const float* x     = (const float*)d_in[0];
    const float* c1w   = (const float*)d_in[1];
    const float* c1b   = (const float*)d_in[2];
    const float* c2w   = (const float*)d_in[3];
    const float* c2b   = (const float*)d_in[4];
    const float* Wcaps = (const float*)d_in[5];
    const float* dw1   = (const float*)d_in[6];
    const float* db1   = (const float*)d_in[7];
    const float* dw2   = (const float*)d_in[8];
    const float* db2   = (const float*)d_in[9];
    const float* dw3   = (const float*)d_in[10];
    const float* db3   = (const float*)d_in[11];
    float* out = (float*)d_out;

    float* g_d1_ptr; cudaGetSymbolAddress((void**)&g_d1_ptr, g_d1);
    float* g_d2_ptr; cudaGetSymbolAddress((void**)&g_d2_ptr, g_d2);
    float* g_m_ptr;  cudaGetSymbolAddress((void**)&g_m_ptr, g_masked);

    cudaFuncSetAttribute(wtrans_kernel, cudaFuncAttributeMaxDynamicSharedMemorySize,
                         32 * 649 * 4);
    cudaFuncSetAttribute(conv2_mma, cudaFuncAttributeMaxDynamicSharedMemorySize, SM_DYN);

    wtrans_kernel<<<256, 256, 32 * 649 * 4>>>(c2w);
    conv1_kernel<<<dim3(256, 2), 128>>>(x, c1w, c1b);
    conv2_mma<<<dim3(72, 2), 256, SM_DYN>>>(c2b);
    squash_conv_kernel<<<1536, 256>>>();
    uhat_kernel2<<<1152, 320>>>(Wcaps);
    routing_kernel<<<256, 256>>>(out);
    gemm_epi<1><<<dim3(8, 4), 256>>>(g_m_ptr, dw1, db1, g_d1_ptr, 256, 512, 160);
    gemm_epi<1><<<dim3(16, 4), 256>>>(g_d1_ptr, dw2, db2, g_d2_ptr, 256, 1024, 512);
    gemm_epi<2><<<dim3(13, 4), 256>>>(g_d2_ptr, dw3, db3, out + 2560, 256, 784, 1024);
}

// round 9
// speedup vs baseline: 1.2802x; 1.2802x over previous
#include <cuda_runtime.h>
#include <cuda_fp16.h>
#include <math.h>
#include <stdint.h>

// ---------------- scratch (device globals: allocation-free contract) ----------------
__device__ __half g_h1[256 * 400 * 256];            // conv1 out [b][y][x][ci] fp16
__device__ __half g_wt[256 * 20736];                // conv2 W   [co][ky*9+kx][ci] fp16
__device__ float g_h2[256 * 9216];                  // conv2 out partial K-half 0 [b][pos][co]
__device__ float g_h2b[256 * 9216];                 // conv2 out partial K-half 1
__device__ float g_u[256 * 9216];                   // squashed  [b][co*36+pos]
__device__ __half g_uhat[(size_t)256 * 1152 * 160]; // u_hat     [b][i][o][d] fp16
__device__ float g_masked[256 * 160];
__device__ float g_d1[256 * 512];
__device__ float g_d2[256 * 1024];

__device__ __forceinline__ void mma_f16(float* c, const uint32_t* a, const uint32_t* b) {
    asm volatile(
        "mma.sync.aligned.m16n8k16.row.col.f32.f16.f16.f32 "
        "{%0,%1,%2,%3}, {%4,%5,%6,%7}, {%8,%9}, {%0,%1,%2,%3};"
        : "+f"(c[0]), "+f"(c[1]), "+f"(c[2]), "+f"(c[3])
        : "r"(a[0]), "r"(a[1]), "r"(a[2]), "r"(a[3]), "r"(b[0]), "r"(b[1]));
}
__device__ __forceinline__ void cp16(uint32_t smem_dst, const void* gsrc) {
    asm volatile("cp.async.cg.shared.global [%0], [%1], 16;" :: "r"(smem_dst), "l"(gsrc));
}
#define CP_COMMIT() asm volatile("cp.async.commit_group;")
#define CP_WAIT2()  asm volatile("cp.async.wait_group 2;")

// ---------------- conv1: [256,1,28,28] -> [b][y][x][co] channel-last fp16 ----------------
__global__ __launch_bounds__(128) void conv1_kernel(
    const float* __restrict__ x, const float* __restrict__ w,
    const float* __restrict__ bias) {
    __shared__ float xs[784];
    __shared__ float ws[128 * 81];
    int b = blockIdx.x;
    int cb = blockIdx.y * 128;
    int t = threadIdx.x;

    for (int idx = t; idx < 784; idx += 128) xs[idx] = x[b * 784 + idx];
    for (int idx = t; idx < 128 * 81; idx += 128) ws[idx] = w[cb * 81 + idx];
    __syncthreads();

    int co = cb + t;
    float bv = bias[co];
    __half* outp = g_h1 + (size_t)b * 400 * 256 + co;

    for (int oy = 0; oy < 20; oy++) {
        float acc[20];
#pragma unroll
        for (int j = 0; j < 20; j++) acc[j] = bv;
        for (int ky = 0; ky < 9; ky++) {
            float xr[28];
#pragma unroll
            for (int j = 0; j < 28; j++) xr[j] = xs[(oy + ky) * 28 + j];
#pragma unroll
            for (int kx = 0; kx < 9; kx++) {
                float wv = ws[t * 81 + ky * 9 + kx];
#pragma unroll
                for (int ox = 0; ox < 20; ox++) acc[ox] += wv * xr[ox + kx];
            }
        }
#pragma unroll
        for (int ox = 0; ox < 20; ox++)
            outp[(oy * 20 + ox) * 256] = __float2half_rn(acc[ox]);
    }
}

// ---------------- conv2 weight transpose -> fp16 [co][ky*9+kx][ci] ----------------
__global__ void wtrans_kernel(const float* __restrict__ Wc) {
    extern __shared__ float s[];  // 20736 floats
    int co = blockIdx.x;
    int t = threadIdx.x;
    const float* src = Wc + (size_t)co * 20736;
    for (int idx = t; idx < 20736; idx += 256) s[idx] = src[idx];
    __syncthreads();
    __half* dst = g_wt + (size_t)co * 20736;
    for (int idx = t; idx < 20736; idx += 256) {
        int j = idx >> 8, ci = idx & 255;
        dst[idx] = __float2half_rn(s[ci * 81 + j]);
    }
}

// ---------------- conv2: fp16 mma m16n8k16, 3-stage cp.async, k-tile 64, split-K 2 ----------------
#define LDT 72                       // halfs per row (64 + 8 pad); 144B
#define LDW 36                       // b32 words per row
#define STAGE_H (128 * LDT)
#define SM_DYN (6 * STAGE_H * 2)     // 110592 bytes

__global__ __launch_bounds__(256, 2) void conv2_mma(const float* __restrict__ bias) {
    extern __shared__ __half smemh[];
    __half* Abuf = smemh;                 // [3][128][LDT]
    __half* Bbuf = smemh + 3 * STAGE_H;   // [3][128][LDT]
    __shared__ int nOffT[128];
    __shared__ int o2Off[128];

    int t = threadIdx.x;
    int bx = blockIdx.x, by = blockIdx.y, bz = blockIdx.z;
    int wid = t >> 5, lane = t & 31;
    int g = lane >> 2, tg = lane & 3;
    int warp_m = wid >> 2, warp_n = wid & 3;

    // K split: bz=0 -> kxy in [0,41); bz=1 -> [41,81)
    const int KXY0 = bz ? 41 : 0;
    const int ITERS = (bz ? 40 : 41) * 4;

    if (t < 128) {
        int n = bx * 128 + t;
        int b = n / 36, pos = n - b * 36;
        int oy = pos / 6, ox = pos - oy * 6;
        nOffT[t] = (b * 400 + oy * 40 + ox * 2) * 256;
        o2Off[t] = (b * 36 + pos) * 256;
    }
    __syncthreads();

    int lrow = t >> 1, lpart = (t & 1) * 32;
    const __half* abase = g_wt + (size_t)(by * 128) * 20736;

    auto issue = [&](int ii) {
        int s = ii % 3;
        int kxy = KXY0 + (ii >> 2), cib = (ii & 3) << 6;
        int ky = kxy / 9, kx = kxy - ky * 9;
        int hoff = (ky * 20 + kx) * 256 + cib;
        __half* As_s = Abuf + s * STAGE_H;
        __half* Bs_s = Bbuf + s * STAGE_H;
        const __half* ga = abase + (size_t)lrow * 20736 + kxy * 256 + cib + lpart;
        const __half* gb = g_h1 + nOffT[lrow] + hoff + lpart;
        uint32_t da = (uint32_t)__cvta_generic_to_shared(As_s + lrow * LDT + lpart);
        uint32_t db = (uint32_t)__cvta_generic_to_shared(Bs_s + lrow * LDT + lpart);
#pragma unroll
        for (int q = 0; q < 4; q++) {
            cp16(da + q * 16, ga + q * 8);
            cp16(db + q * 16, gb + q * 8);
        }
        CP_COMMIT();
    };

    issue(0); issue(1); issue(2);

    float acc[4][4][4];
#pragma unroll
    for (int mi = 0; mi < 4; mi++)
#pragma unroll
        for (int ni = 0; ni < 4; ni++)
#pragma unroll
            for (int r = 0; r < 4; r++) acc[mi][ni][r] = 0.f;

    for (int i = 0; i < ITERS; i++) {
        CP_WAIT2();
        __syncthreads();

        const uint32_t* As_w = (const uint32_t*)(Abuf + (i % 3) * STAGE_H);
        const uint32_t* Bs_w = (const uint32_t*)(Bbuf + (i % 3) * STAGE_H);

#pragma unroll
        for (int ks = 0; ks < 4; ks++) {
            int kw = ks * 8 + tg;
            uint32_t a_f[4][4];
            uint32_t b_f[4][2];
#pragma unroll
            for (int mi = 0; mi < 4; mi++) {
                int m0 = warp_m * 64 + mi * 16 + g;
                a_f[mi][0] = As_w[m0 * LDW + kw];
                a_f[mi][1] = As_w[(m0 + 8) * LDW + kw];
                a_f[mi][2] = As_w[m0 * LDW + kw + 4];
                a_f[mi][3] = As_w[(m0 + 8) * LDW + kw + 4];
            }
#pragma unroll
            for (int ni = 0; ni < 4; ni++) {
                int n0 = warp_n * 32 + ni * 8 + g;
                b_f[ni][0] = Bs_w[n0 * LDW + kw];
                b_f[ni][1] = Bs_w[n0 * LDW + kw + 4];
            }
#pragma unroll
            for (int mi = 0; mi < 4; mi++)
#pragma unroll
                for (int ni = 0; ni < 4; ni++)
                    mma_f16(acc[mi][ni], a_f[mi], b_f[ni]);
        }
        __syncthreads();

        if (i + 3 < ITERS) issue(i + 3);
        else CP_COMMIT();
    }

    // epilogue: scatter partial to its K-half buffer; bias folded into half 0
    float* outb = bz ? g_h2b : g_h2;
#pragma unroll
    for (int mi = 0; mi < 4; mi++) {
        int m0 = warp_m * 64 + mi * 16 + g;
        int mg0 = by * 128 + m0;
        float bv0 = bz ? 0.f : bias[mg0];
        float bv1 = bz ? 0.f : bias[mg0 + 8];
#pragma unroll
        for (int ni = 0; ni < 4; ni++) {
            int n0 = warp_n * 32 + ni * 8 + 2 * tg;
            int o0 = o2Off[n0], o1 = o2Off[n0 + 1];
            outb[o0 + mg0]     = acc[mi][ni][0] + bv0;
            outb[o1 + mg0]     = acc[mi][ni][1] + bv0;
            outb[o0 + mg0 + 8] = acc[mi][ni][2] + bv1;
            outb[o1 + mg0 + 8] = acc[mi][ni][3] + bv1;
        }
    }
}

// ---------------- squash over last spatial axis (sums the two K-halves) ----------------
__global__ void squash_conv_kernel() {
    int gid = blockIdx.x * blockDim.x + threadIdx.x;  // 393216
    int b = gid / 1536;
    int rem = gid - b * 1536;
    int oy = rem >> 8;
    int co = rem & 255;
    float v[6];
    float n2 = 0.f;
#pragma unroll
    for (int j = 0; j < 6; j++) {
        size_t idx = (size_t)(b * 36 + oy * 6 + j) * 256 + co;
        v[j] = g_h2[idx] + g_h2b[idx];
        n2 += v[j] * v[j];
    }
    float nrm = sqrtf(n2);
    float sc = (n2 / (1.f + n2)) / (nrm + 1e-7f);
    float* q = g_u + (size_t)b * 9216 + co * 36 + oy * 6;
#pragma unroll
    for (int j = 0; j < 6; j++) q[j] = v[j] * sc;
}

// ---------------- u_hat (fp16 out): block = input capsule i ----------------
__global__ __launch_bounds__(320) void uhat_kernel2(const float* __restrict__ Wc) {
    __shared__ float u_s[2048];
    int i = blockIdx.x;
    int t = threadIdx.x;
    int b2 = t / 40;
    int od4 = t - b2 * 40;

    for (int idx = t; idx < 2048; idx += 320) {
        int b = idx >> 3, e = idx & 7;
        u_s[idx] = g_u[(size_t)b * 9216 + i * 8 + e];
    }
    int od0 = od4 * 4;
    int o = od0 >> 4;
    int d0 = od0 & 15;
    const float* wp = Wc + ((size_t)(o * 1152 + i) * 16 + d0) * 8;
    float w[4][8];
#pragma unroll
    for (int q = 0; q < 4; q++) {
        float4 w0 = *(const float4*)(wp + q * 8);
        float4 w1 = *(const float4*)(wp + q * 8 + 4);
        w[q][0] = w0.x; w[q][1] = w0.y; w[q][2] = w0.z; w[q][3] = w0.w;
        w[q][4] = w1.x; w[q][5] = w1.y; w[q][6] = w1.z; w[q][7] = w1.w;
    }
    __syncthreads();
    for (int bo = 0; bo < 32; bo++) {
        int b = bo * 8 + b2;
        float ue[8];
#pragma unroll
        for (int e = 0; e < 8; e++) ue[e] = u_s[b * 8 + e];
        float acc[4];
#pragma unroll
        for (int q = 0; q < 4; q++) {
            float a = 0.f;
#pragma unroll
            for (int e = 0; e < 8; e++) a += w[q][e] * ue[e];
            acc[q] = a;
        }
        __half2 h0 = __floats2half2_rn(acc[0], acc[1]);
        __half2 h1 = __floats2half2_rn(acc[2], acc[3]);
        __half2* dst = (__half2*)(g_uhat + ((size_t)b * 1152 + i) * 160 + od0);
        dst[0] = h0; dst[1] = h1;
    }
}

// ---------------- dynamic routing (3 iters fused), fp16 u_hat ----------------
__device__ __forceinline__ void route_accum(
    const float uh[5], const float* v0s, const float* v1s,
    int p, int lane, float sacc[5]) {
    float c[5];
    float lg[5];
#pragma unroll
    for (int og = 0; og < 5; og++) {
        float tsum = uh[og] * v0s[og * 32 + lane];
        if (p == 2) tsum += uh[og] * v1s[og * 32 + lane];
        tsum += __shfl_xor_sync(0xffffffffu, tsum, 8);
        tsum += __shfl_xor_sync(0xffffffffu, tsum, 4);
        tsum += __shfl_xor_sync(0xffffffffu, tsum, 2);
        tsum += __shfl_xor_sync(0xffffffffu, tsum, 1);
        lg[og] = tsum;
    }
    float m = lg[0];
#pragma unroll
    for (int og = 1; og < 5; og++) m = fmaxf(m, lg[og]);
    m = fmaxf(m, __shfl_xor_sync(0xffffffffu, m, 16));
    float ssum = 0.f;
#pragma unroll
    for (int og = 0; og < 5; og++) { c[og] = expf(lg[og] - m); ssum += c[og]; }
    ssum += __shfl_xor_sync(0xffffffffu, ssum, 16);
    float inv = 1.f / ssum;
#pragma unroll
    for (int og = 0; og < 5; og++) sacc[og] += (c[og] * inv) * uh[og];
}

__global__ __launch_bounds__(256) void routing_kernel(float* __restrict__ out_len) {
    int b = blockIdx.x;
    int tid = threadIdx.x;
    int lane = tid & 31, warp = tid >> 5;

    __shared__ float v0s[160], v1s[160], v2s[160];
    __shared__ float spart[8 * 160];
    __shared__ float sred[160];
    __shared__ float scale_s[10], len_s[10];
    __shared__ int amax_s;

    const __half* base = g_uhat + (size_t)b * 184320;

    for (int p = 0; p < 3; p++) {
        float sacc[5] = {0.f, 0.f, 0.f, 0.f, 0.f};
        for (int ii = warp; ii < 1152; ii += 16) {
            const __half* pA = base + ii * 160;
            const __half* pB = base + (ii + 8) * 160;
            float uhA[5], uhB[5];
#pragma unroll
            for (int og = 0; og < 5; og++) uhA[og] = __half2float(pA[og * 32 + lane]);
#pragma unroll
            for (int og = 0; og < 5; og++) uhB[og] = __half2float(pB[og * 32 + lane]);
            if (p == 0) {
#pragma unroll
                for (int og = 0; og < 5; og++) sacc[og] += 0.1f * (uhA[og] + uhB[og]);
            } else {
                route_accum(uhA, v0s, v1s, p, lane, sacc);
                route_accum(uhB, v0s, v1s, p, lane, sacc);
            }
        }
#pragma unroll
        for (int og = 0; og < 5; og++) spart[warp * 160 + og * 32 + lane] = sacc[og];
        __syncthreads();
        if (tid < 160) {
            float tot = 0.f;
#pragma unroll
            for (int w = 0; w < 8; w++) tot += spart[w * 160 + tid];
            sred[tid] = tot;
        }
        __syncthreads();
        if (tid < 10) {
            float n2 = 0.f;
#pragma unroll
            for (int d = 0; d < 16; d++) { float xv = sred[tid * 16 + d]; n2 += xv * xv; }
            float nrm = sqrtf(n2);
            scale_s[tid] = (n2 / (1.f + n2)) / (nrm + 1e-7f);
            if (p == 2) len_s[tid] = (n2 / (1.f + n2)) * (nrm / (nrm + 1e-7f));
        }
        __syncthreads();
        float* vdst = (p == 0) ? v0s : ((p == 1) ? v1s : v2s);
        if (tid < 160) vdst[tid] = sred[tid] * scale_s[tid >> 4];
        __syncthreads();
    }

    if (tid == 0) {
        int bi = 0;
        float best = len_s[0];
#pragma unroll
        for (int o = 1; o < 10; o++)
            if (len_s[o] > best) { best = len_s[o]; bi = o; }
        amax_s = bi;
    }
    if (tid < 10) out_len[b * 10 + tid] = len_s[tid];
    __syncthreads();
    if (tid < 160) g_masked[b * 160 + tid] = ((tid >> 4) == amax_s) ? v2s[tid] : 0.f;
}

// ---------------- decoder GEMM (64x64x16 tile, 4x4 micro), epilogue fused ----------------
template <int EPI>
__global__ __launch_bounds__(256) void gemm_epi(
    const float* __restrict__ A, const float* __restrict__ W,
    const float* __restrict__ bias, float* __restrict__ C,
    int M, int N, int K) {
    __shared__ float As[16][64];
    __shared__ float Bs[16][64];
    int t = threadIdx.x;
    int bx = blockIdx.x, by = blockIdx.y;
    int arow = t >> 2, ak = (t & 3) * 4;
    int bkr = t >> 4, bnc = (t & 15) * 4;
    int tx = t & 15, ty = t >> 4;

    float acc[4][4];
#pragma unroll
    for (int i = 0; i < 4; i++)
#pragma unroll
        for (int j = 0; j < 4; j++) acc[i][j] = 0.f;

    for (int kk = 0; kk < K; kk += 16) {
        float4 av = *(const float4*)(A + (size_t)(by * 64 + arow) * K + kk + ak);
        int n0 = bx * 64 + bnc;
        float4 bv = make_float4(0.f, 0.f, 0.f, 0.f);
        if (n0 < N) bv = *(const float4*)(W + (size_t)(kk + bkr) * N + n0);
        As[ak + 0][arow] = av.x; As[ak + 1][arow] = av.y;
        As[ak + 2][arow] = av.z; As[ak + 3][arow] = av.w;
        *(float4*)&Bs[bkr][bnc] = bv;
        __syncthreads();
#pragma unroll
        for (int kr = 0; kr < 16; kr++) {
            float af[4], bf[4];
            *(float4*)af = *(const float4*)&As[kr][ty * 4];
            *(float4*)bf = *(const float4*)&Bs[kr][tx * 4];
#pragma unroll
            for (int mi = 0; mi < 4; mi++)
#pragma unroll
                for (int ni = 0; ni < 4; ni++) acc[mi][ni] += af[mi] * bf[ni];
        }
        __syncthreads();
    }

#pragma unroll
    for (int mi = 0; mi < 4; mi++) {
        int m = by * 64 + ty * 4 + mi;
#pragma unroll
        for (int ni = 0; ni < 4; ni++) {
            int n = bx * 64 + tx * 4 + ni;
            if (n < N) {
                float v = acc[mi][ni] + bias[n];
                if (EPI == 1) v = fmaxf(v, 0.f);
                if (EPI == 2) v = 1.f / (1.f + expf(-v));
                C[(size_t)m * N + n] = v;
            }
        }
    }
}

// ---------------- launch ----------------
extern "C" void kernel_launch(void* const* d_in, const int* in_sizes, int n_in,
                              void* d_out, int out_size) {
    const float* x     = (const float*)d_in[0];
    const float* c1w   = (const float*)d_in[1];
    const float* c1b   = (const float*)d_in[2];
    const float* c2w   = (const float*)d_in[3];
    const float* c2b   = (const float*)d_in[4];
    const float* Wcaps = (const float*)d_in[5];
    const float* dw1   = (const float*)d_in[6];
    const float* db1   = (const float*)d_in[7];
    const float* dw2   = (const float*)d_in[8];
    const float* db2   = (const float*)d_in[9];
    const float* dw3   = (const float*)d_in[10];
    const float* db3   = (const float*)d_in[11];
    float* out = (float*)d_out;

    float* g_d1_ptr; cudaGetSymbolAddress((void**)&g_d1_ptr, g_d1);
    float* g_d2_ptr; cudaGetSymbolAddress((void**)&g_d2_ptr, g_d2);
    float* g_m_ptr;  cudaGetSymbolAddress((void**)&g_m_ptr, g_masked);

    cudaFuncSetAttribute(wtrans_kernel, cudaFuncAttributeMaxDynamicSharedMemorySize,
                         20736 * 4);
    cudaFuncSetAttribute(conv2_mma, cudaFuncAttributeMaxDynamicSharedMemorySize, SM_DYN);

    wtrans_kernel<<<256, 256, 20736 * 4>>>(c2w);
    conv1_kernel<<<dim3(256, 2), 128>>>(x, c1w, c1b);
    conv2_mma<<<dim3(72, 2, 2), 256, SM_DYN>>>(c2b);
    squash_conv_kernel<<<1536, 256>>>();
    uhat_kernel2<<<1152, 320>>>(Wcaps);
    routing_kernel<<<256, 256>>>(out);
    gemm_epi<1><<<dim3(8, 4), 256>>>(g_m_ptr, dw1, db1, g_d1_ptr, 256, 512, 160);
    gemm_epi<1><<<dim3(16, 4), 256>>>(g_d1_ptr, dw2, db2, g_d2_ptr, 256, 1024, 512);
    gemm_epi<2><<<dim3(13, 4), 256>>>(g_d2_ptr, dw3, db3, out + 2560, 256, 784, 1024);
}

// round 10
// speedup vs baseline: 1.3677x; 1.0684x over previous
#include <cuda_runtime.h>
#include <cuda_fp16.h>
#include <math.h>
#include <stdint.h>

// ---------------- scratch (device globals: allocation-free contract) ----------------
__device__ __half g_h1[256 * 400 * 256];            // conv1 out [b][y][x][ci] fp16
__device__ __half g_wt[256 * 20736];                // conv2 W   [co][ky*9+kx][ci] fp16
__device__ float g_h2[256 * 9216];                  // conv2 out partial K-half 0 [b][pos][co]
__device__ float g_h2b[256 * 9216];                 // conv2 out partial K-half 1
__device__ float g_u[256 * 9216];                   // squashed  [b][co*36+pos]
__device__ __half g_uhat[(size_t)256 * 1152 * 160]; // u_hat     [b][i][o][d] fp16
__device__ float g_s0p[256 * 8 * 160];              // pass-0 partial sums
__device__ float g_masked[256 * 160];
__device__ float g_d1[256 * 512];
__device__ float g_d2[256 * 1024];

__device__ __forceinline__ void mma_f16(float* c, const uint32_t* a, const uint32_t* b) {
    asm volatile(
        "mma.sync.aligned.m16n8k16.row.col.f32.f16.f16.f32 "
        "{%0,%1,%2,%3}, {%4,%5,%6,%7}, {%8,%9}, {%0,%1,%2,%3};"
        : "+f"(c[0]), "+f"(c[1]), "+f"(c[2]), "+f"(c[3])
        : "r"(a[0]), "r"(a[1]), "r"(a[2]), "r"(a[3]), "r"(b[0]), "r"(b[1]));
}
__device__ __forceinline__ void ldsm4(uint32_t* r, uint32_t addr) {
    asm volatile("ldmatrix.sync.aligned.m8n8.x4.shared.b16 {%0,%1,%2,%3}, [%4];"
        : "=r"(r[0]), "=r"(r[1]), "=r"(r[2]), "=r"(r[3]) : "r"(addr));
}
__device__ __forceinline__ void cp16(uint32_t smem_dst, const void* gsrc) {
    asm volatile("cp.async.cg.shared.global [%0], [%1], 16;" :: "r"(smem_dst), "l"(gsrc));
}
#define CP_COMMIT() asm volatile("cp.async.commit_group;")
#define CP_WAIT2()  asm volatile("cp.async.wait_group 2;")

// ---------------- conv1: [256,1,28,28] -> [b][y][x][co] channel-last fp16 ----------------
__global__ __launch_bounds__(128) void conv1_kernel(
    const float* __restrict__ x, const float* __restrict__ w,
    const float* __restrict__ bias) {
    __shared__ float xs[784];
    __shared__ float ws[128 * 81];
    int b = blockIdx.x;
    int cb = blockIdx.y * 128;
    int t = threadIdx.x;

    for (int idx = t; idx < 784; idx += 128) xs[idx] = x[b * 784 + idx];
    for (int idx = t; idx < 128 * 81; idx += 128) ws[idx] = w[cb * 81 + idx];
    __syncthreads();

    int co = cb + t;
    float bv = bias[co];
    __half* outp = g_h1 + (size_t)b * 400 * 256 + co;

    for (int oy = 0; oy < 20; oy++) {
        float acc[20];
#pragma unroll
        for (int j = 0; j < 20; j++) acc[j] = bv;
        for (int ky = 0; ky < 9; ky++) {
            float xr[28];
#pragma unroll
            for (int j = 0; j < 28; j++) xr[j] = xs[(oy + ky) * 28 + j];
#pragma unroll
            for (int kx = 0; kx < 9; kx++) {
                float wv = ws[t * 81 + ky * 9 + kx];
#pragma unroll
                for (int ox = 0; ox < 20; ox++) acc[ox] += wv * xr[ox + kx];
            }
        }
#pragma unroll
        for (int ox = 0; ox < 20; ox++)
            outp[(oy * 20 + ox) * 256] = __float2half_rn(acc[ox]);
    }
}

// ---------------- conv2 weight transpose -> fp16 [co][ky*9+kx][ci] ----------------
__global__ void wtrans_kernel(const float* __restrict__ Wc) {
    extern __shared__ float s[];  // 20736 floats
    int co = blockIdx.x;
    int t = threadIdx.x;
    const float* src = Wc + (size_t)co * 20736;
    for (int idx = t; idx < 20736; idx += 256) s[idx] = src[idx];
    __syncthreads();
    __half* dst = g_wt + (size_t)co * 20736;
    for (int idx = t; idx < 20736; idx += 256) {
        int j = idx >> 8, ci = idx & 255;
        dst[idx] = __float2half_rn(s[ci * 81 + j]);
    }
}

// ---------------- conv2: fp16 mma m16n8k16, 3-stage cp.async, split-K 2, ldmatrix A ----------------
#define LDT 72                       // halfs per row (64 + 8 pad); 144B
#define LDW 36                       // b32 words per row
#define STAGE_H (128 * LDT)
#define SM_DYN (6 * STAGE_H * 2)     // 110592 bytes

__global__ __launch_bounds__(256, 2) void conv2_mma(const float* __restrict__ bias) {
    extern __shared__ __half smemh[];
    __half* Abuf = smemh;                 // [3][128][LDT]
    __half* Bbuf = smemh + 3 * STAGE_H;   // [3][128][LDT]
    __shared__ int nOffT[128];
    __shared__ int o2Off[128];

    int t = threadIdx.x;
    int bx = blockIdx.x, by = blockIdx.y, bz = blockIdx.z;
    int wid = t >> 5, lane = t & 31;
    int g = lane >> 2, tg = lane & 3;
    int warp_m = wid >> 2, warp_n = wid & 3;

    const int KXY0 = bz ? 41 : 0;
    const int ITERS = (bz ? 40 : 41) * 4;

    if (t < 128) {
        int n = bx * 128 + t;
        int b = n / 36, pos = n - b * 36;
        int oy = pos / 6, ox = pos - oy * 6;
        nOffT[t] = (b * 400 + oy * 40 + ox * 2) * 256;
        o2Off[t] = (b * 36 + pos) * 256;
    }
    __syncthreads();

    int lrow = t >> 1, lpart = (t & 1) * 32;
    const __half* abase = g_wt + (size_t)(by * 128) * 20736;

    auto issue = [&](int ii) {
        int s = ii % 3;
        int kxy = KXY0 + (ii >> 2), cib = (ii & 3) << 6;
        int ky = kxy / 9, kx = kxy - ky * 9;
        int hoff = (ky * 20 + kx) * 256 + cib;
        __half* As_s = Abuf + s * STAGE_H;
        __half* Bs_s = Bbuf + s * STAGE_H;
        const __half* ga = abase + (size_t)lrow * 20736 + kxy * 256 + cib + lpart;
        const __half* gb = g_h1 + nOffT[lrow] + hoff + lpart;
        uint32_t da = (uint32_t)__cvta_generic_to_shared(As_s + lrow * LDT + lpart);
        uint32_t db = (uint32_t)__cvta_generic_to_shared(Bs_s + lrow * LDT + lpart);
#pragma unroll
        for (int q = 0; q < 4; q++) {
            cp16(da + q * 16, ga + q * 8);
            cp16(db + q * 16, gb + q * 8);
        }
        CP_COMMIT();
    };

    issue(0); issue(1); issue(2);

    // ldmatrix A base: lane&15 -> row within 16-row block, lane>>4 -> k-half (8 halfs)
    uint32_t a_base = (uint32_t)__cvta_generic_to_shared(Abuf) +
        (uint32_t)(((warp_m * 64 + (lane & 15)) * LDT + (lane >> 4) * 8) * 2);

    float acc[4][4][4];
#pragma unroll
    for (int mi = 0; mi < 4; mi++)
#pragma unroll
        for (int ni = 0; ni < 4; ni++)
#pragma unroll
            for (int r = 0; r < 4; r++) acc[mi][ni][r] = 0.f;

    for (int i = 0; i < ITERS; i++) {
        CP_WAIT2();
        __syncthreads();

        uint32_t aS = a_base + (uint32_t)((i % 3) * (STAGE_H * 2));
        const uint32_t* Bs_w = (const uint32_t*)(Bbuf + (i % 3) * STAGE_H);

#pragma unroll
        for (int ks = 0; ks < 4; ks++) {
            int kw = ks * 8 + tg;
            uint32_t a_f[4][4];
            uint32_t b_f[4][2];
#pragma unroll
            for (int mi = 0; mi < 4; mi++)
                ldsm4(a_f[mi], aS + (uint32_t)((mi * 16 * LDT + ks * 16) * 2));
#pragma unroll
            for (int ni = 0; ni < 4; ni++) {
                int n0 = warp_n * 32 + ni * 8 + g;
                b_f[ni][0] = Bs_w[n0 * LDW + kw];
                b_f[ni][1] = Bs_w[n0 * LDW + kw + 4];
            }
#pragma unroll
            for (int mi = 0; mi < 4; mi++)
#pragma unroll
                for (int ni = 0; ni < 4; ni++)
                    mma_f16(acc[mi][ni], a_f[mi], b_f[ni]);
        }
        __syncthreads();

        if (i + 3 < ITERS) issue(i + 3);
        else CP_COMMIT();
    }

    float* outb = bz ? g_h2b : g_h2;
#pragma unroll
    for (int mi = 0; mi < 4; mi++) {
        int m0 = warp_m * 64 + mi * 16 + g;
        int mg0 = by * 128 + m0;
        float bv0 = bz ? 0.f : bias[mg0];
        float bv1 = bz ? 0.f : bias[mg0 + 8];
#pragma unroll
        for (int ni = 0; ni < 4; ni++) {
            int n0 = warp_n * 32 + ni * 8 + 2 * tg;
            int o0 = o2Off[n0], o1 = o2Off[n0 + 1];
            outb[o0 + mg0]     = acc[mi][ni][0] + bv0;
            outb[o1 + mg0]     = acc[mi][ni][1] + bv0;
            outb[o0 + mg0 + 8] = acc[mi][ni][2] + bv1;
            outb[o1 + mg0 + 8] = acc[mi][ni][3] + bv1;
        }
    }
}

// ---------------- squash over last spatial axis (sums the two K-halves) ----------------
__global__ void squash_conv_kernel() {
    int gid = blockIdx.x * blockDim.x + threadIdx.x;  // 393216
    int b = gid / 1536;
    int rem = gid - b * 1536;
    int oy = rem >> 8;
    int co = rem & 255;
    float v[6];
    float n2 = 0.f;
#pragma unroll
    for (int j = 0; j < 6; j++) {
        size_t idx = (size_t)(b * 36 + oy * 6 + j) * 256 + co;
        v[j] = g_h2[idx] + g_h2b[idx];
        n2 += v[j] * v[j];
    }
    float nrm = sqrtf(n2);
    float sc = (n2 / (1.f + n2)) / (nrm + 1e-7f);
    float* q = g_u + (size_t)b * 9216 + co * 36 + oy * 6;
#pragma unroll
    for (int j = 0; j < 6; j++) q[j] = v[j] * sc;
}

// ---------------- u_hat (fp16 out): block = input capsule i ----------------
__global__ __launch_bounds__(320) void uhat_kernel2(const float* __restrict__ Wc) {
    __shared__ float u_s[2048];
    int i = blockIdx.x;
    int t = threadIdx.x;
    int b2 = t / 40;
    int od4 = t - b2 * 40;

    for (int idx = t; idx < 2048; idx += 320) {
        int b = idx >> 3, e = idx & 7;
        u_s[idx] = g_u[(size_t)b * 9216 + i * 8 + e];
    }
    int od0 = od4 * 4;
    int o = od0 >> 4;
    int d0 = od0 & 15;
    const float* wp = Wc + ((size_t)(o * 1152 + i) * 16 + d0) * 8;
    float w[4][8];
#pragma unroll
    for (int q = 0; q < 4; q++) {
        float4 w0 = *(const float4*)(wp + q * 8);
        float4 w1 = *(const float4*)(wp + q * 8 + 4);
        w[q][0] = w0.x; w[q][1] = w0.y; w[q][2] = w0.z; w[q][3] = w0.w;
        w[q][4] = w1.x; w[q][5] = w1.y; w[q][6] = w1.z; w[q][7] = w1.w;
    }
    __syncthreads();
    for (int bo = 0; bo < 32; bo++) {
        int b = bo * 8 + b2;
        float ue[8];
#pragma unroll
        for (int e = 0; e < 8; e++) ue[e] = u_s[b * 8 + e];
        float acc[4];
#pragma unroll
        for (int q = 0; q < 4; q++) {
            float a = 0.f;
#pragma unroll
            for (int e = 0; e < 8; e++) a += w[q][e] * ue[e];
            acc[q] = a;
        }
        __half2 h0 = __floats2half2_rn(acc[0], acc[1]);
        __half2 h1 = __floats2half2_rn(acc[2], acc[3]);
        __half2* dst = (__half2*)(g_uhat + ((size_t)b * 1152 + i) * 160 + od0);
        dst[0] = h0; dst[1] = h1;
    }
}

// ---------------- pass-0 partial sums: g_s0p[b][c][od] = sum_{i in chunk c} u_hat ----------------
__global__ __launch_bounds__(160) void uhat_sum_kernel() {
    int b = blockIdx.x, c = blockIdx.y;
    int t = threadIdx.x;
    const __half* p = g_uhat + ((size_t)b * 1152 + c * 144) * 160 + t;
    float acc = 0.f;
#pragma unroll 4
    for (int i = 0; i < 144; i++) acc += __half2float(p[(size_t)i * 160]);
    g_s0p[(b * 8 + c) * 160 + t] = acc;
}

// ---------------- dynamic routing (passes 1,2; pass 0 from partials), 512 threads ----------------
__device__ __forceinline__ void route_accum(
    const float uh[5], const float* v0s, const float* v1s,
    int p, int lane, float sacc[5]) {
    float c[5];
    float lg[5];
#pragma unroll
    for (int og = 0; og < 5; og++) {
        float tsum = uh[og] * v0s[og * 32 + lane];
        if (p == 2) tsum += uh[og] * v1s[og * 32 + lane];
        tsum += __shfl_xor_sync(0xffffffffu, tsum, 8);
        tsum += __shfl_xor_sync(0xffffffffu, tsum, 4);
        tsum += __shfl_xor_sync(0xffffffffu, tsum, 2);
        tsum += __shfl_xor_sync(0xffffffffu, tsum, 1);
        lg[og] = tsum;
    }
    float m = lg[0];
#pragma unroll
    for (int og = 1; og < 5; og++) m = fmaxf(m, lg[og]);
    m = fmaxf(m, __shfl_xor_sync(0xffffffffu, m, 16));
    float ssum = 0.f;
#pragma unroll
    for (int og = 0; og < 5; og++) { c[og] = expf(lg[og] - m); ssum += c[og]; }
    ssum += __shfl_xor_sync(0xffffffffu, ssum, 16);
    float inv = 1.f / ssum;
#pragma unroll
    for (int og = 0; og < 5; og++) sacc[og] += (c[og] * inv) * uh[og];
}

__global__ __launch_bounds__(512) void routing_kernel(float* __restrict__ out_len) {
    int b = blockIdx.x;
    int tid = threadIdx.x;
    int lane = tid & 31, warp = tid >> 5;   // 16 warps

    __shared__ float v0s[160], v1s[160], v2s[160];
    __shared__ float spart[16 * 160];
    __shared__ float sred[160];
    __shared__ float scale_s[10], len_s[10];
    __shared__ int amax_s;

    const __half* base = g_uhat + (size_t)b * 184320;

    // ---- pass 0 from precomputed partials ----
    if (tid < 160) {
        float tot = 0.f;
#pragma unroll
        for (int c = 0; c < 8; c++) tot += g_s0p[(b * 8 + c) * 160 + tid];
        sred[tid] = 0.1f * tot;
    }
    __syncthreads();
    if (tid < 10) {
        float n2 = 0.f;
#pragma unroll
        for (int d = 0; d < 16; d++) { float xv = sred[tid * 16 + d]; n2 += xv * xv; }
        float nrm = sqrtf(n2);
        scale_s[tid] = (n2 / (1.f + n2)) / (nrm + 1e-7f);
    }
    __syncthreads();
    if (tid < 160) v0s[tid] = sred[tid] * scale_s[tid >> 4];
    __syncthreads();

    // ---- passes 1, 2 ----
    for (int p = 1; p < 3; p++) {
        float sacc[5] = {0.f, 0.f, 0.f, 0.f, 0.f};
        for (int ii = warp; ii < 1152; ii += 32) {
            const __half* pA = base + ii * 160;
            const __half* pB = base + (ii + 16) * 160;
            float uhA[5], uhB[5];
#pragma unroll
            for (int og = 0; og < 5; og++) uhA[og] = __half2float(pA[og * 32 + lane]);
#pragma unroll
            for (int og = 0; og < 5; og++) uhB[og] = __half2float(pB[og * 32 + lane]);
            route_accum(uhA, v0s, v1s, p, lane, sacc);
            route_accum(uhB, v0s, v1s, p, lane, sacc);
        }
#pragma unroll
        for (int og = 0; og < 5; og++) spart[warp * 160 + og * 32 + lane] = sacc[og];
        __syncthreads();
        if (tid < 160) {
            float tot = 0.f;
#pragma unroll
            for (int w = 0; w < 16; w++) tot += spart[w * 160 + tid];
            sred[tid] = tot;
        }
        __syncthreads();
        if (tid < 10) {
            float n2 = 0.f;
#pragma unroll
            for (int d = 0; d < 16; d++) { float xv = sred[tid * 16 + d]; n2 += xv * xv; }
            float nrm = sqrtf(n2);
            scale_s[tid] = (n2 / (1.f + n2)) / (nrm + 1e-7f);
            if (p == 2) len_s[tid] = (n2 / (1.f + n2)) * (nrm / (nrm + 1e-7f));
        }
        __syncthreads();
        float* vdst = (p == 1) ? v1s : v2s;
        if (tid < 160) vdst[tid] = sred[tid] * scale_s[tid >> 4];
        __syncthreads();
    }

    if (tid == 0) {
        int bi = 0;
        float best = len_s[0];
#pragma unroll
        for (int o = 1; o < 10; o++)
            if (len_s[o] > best) { best = len_s[o]; bi = o; }
        amax_s = bi;
    }
    if (tid < 10) out_len[b * 10 + tid] = len_s[tid];
    __syncthreads();
    if (tid < 160) g_masked[b * 160 + tid] = ((tid >> 4) == amax_s) ? v2s[tid] : 0.f;
}

// ---------------- decoder GEMM (64x64x16 tile, 4x4 micro), epilogue fused ----------------
template <int EPI>
__global__ __launch_bounds__(256) void gemm_epi(
    const float* __restrict__ A, const float* __restrict__ W,
    const float* __restrict__ bias, float* __restrict__ C,
    int M, int N, int K) {
    __shared__ float As[16][64];
    __shared__ float Bs[16][64];
    int t = threadIdx.x;
    int bx = blockIdx.x, by = blockIdx.y;
    int arow = t >> 2, ak = (t & 3) * 4;
    int bkr = t >> 4, bnc = (t & 15) * 4;
    int tx = t & 15, ty = t >> 4;

    float acc[4][4];
#pragma unroll
    for (int i = 0; i < 4; i++)
#pragma unroll
        for (int j = 0; j < 4; j++) acc[i][j] = 0.f;

    for (int kk = 0; kk < K; kk += 16) {
        float4 av = *(const float4*)(A + (size_t)(by * 64 + arow) * K + kk + ak);
        int n0 = bx * 64 + bnc;
        float4 bv = make_float4(0.f, 0.f, 0.f, 0.f);
        if (n0 < N) bv = *(const float4*)(W + (size_t)(kk + bkr) * N + n0);
        As[ak + 0][arow] = av.x; As[ak + 1][arow] = av.y;
        As[ak + 2][arow] = av.z; As[ak + 3][arow] = av.w;
        *(float4*)&Bs[bkr][bnc] = bv;
        __syncthreads();
#pragma unroll
        for (int kr = 0; kr < 16; kr++) {
            float af[4], bf[4];
            *(float4*)af = *(const float4*)&As[kr][ty * 4];
            *(float4*)bf = *(const float4*)&Bs[kr][tx * 4];
#pragma unroll
            for (int mi = 0; mi < 4; mi++)
#pragma unroll
                for (int ni = 0; ni < 4; ni++) acc[mi][ni] += af[mi] * bf[ni];
        }
        __syncthreads();
    }

#pragma unroll
    for (int mi = 0; mi < 4; mi++) {
        int m = by * 64 + ty * 4 + mi;
#pragma unroll
        for (int ni = 0; ni < 4; ni++) {
            int n = bx * 64 + tx * 4 + ni;
            if (n < N) {
                float v = acc[mi][ni] + bias[n];
                if (EPI == 1) v = fmaxf(v, 0.f);
                if (EPI == 2) v = 1.f / (1.f + expf(-v));
                C[(size_t)m * N + n] = v;
            }
        }
    }
}

// ---------------- launch ----------------
extern "C" void kernel_launch(void* const* d_in, const int* in_sizes, int n_in,
                              void* d_out, int out_size) {
    const float* x     = (const float*)d_in[0];
    const float* c1w   = (const float*)d_in[1];
    const float* c1b   = (const float*)d_in[2];
    const float* c2w   = (const float*)d_in[3];
    const float* c2b   = (const float*)d_in[4];
    const float* Wcaps = (const float*)d_in[5];
    const float* dw1   = (const float*)d_in[6];
    const float* db1   = (const float*)d_in[7];
    const float* dw2   = (const float*)d_in[8];
    const float* db2   = (const float*)d_in[9];
    const float* dw3   = (const float*)d_in[10];
    const float* db3   = (const float*)d_in[11];
    float* out = (float*)d_out;

    float* g_d1_ptr; cudaGetSymbolAddress((void**)&g_d1_ptr, g_d1);
    float* g_d2_ptr; cudaGetSymbolAddress((void**)&g_d2_ptr, g_d2);
    float* g_m_ptr;  cudaGetSymbolAddress((void**)&g_m_ptr, g_masked);

    cudaFuncSetAttribute(wtrans_kernel, cudaFuncAttributeMaxDynamicSharedMemorySize,
                         20736 * 4);
    cudaFuncSetAttribute(conv2_mma, cudaFuncAttributeMaxDynamicSharedMemorySize, SM_DYN);

    wtrans_kernel<<<256, 256, 20736 * 4>>>(c2w);
    conv1_kernel<<<dim3(256, 2), 128>>>(x, c1w, c1b);
    conv2_mma<<<dim3(72, 2, 2), 256, SM_DYN>>>(c2b);
    squash_conv_kernel<<<1536, 256>>>();
    uhat_kernel2<<<1152, 320>>>(Wcaps);
    uhat_sum_kernel<<<dim3(256, 8), 160>>>();
    routing_kernel<<<256, 512>>>(out);
    gemm_epi<1><<<dim3(8, 4), 256>>>(g_m_ptr, dw1, db1, g_d1_ptr, 256, 512, 160);
    gemm_epi<1><<<dim3(16, 4), 256>>>(g_d1_ptr, dw2, db2, g_d2_ptr, 256, 1024, 512);
    gemm_epi<2><<<dim3(13, 4), 256>>>(g_d2_ptr, dw3, db3, out + 2560, 256, 784, 1024);
}

// round 11
// speedup vs baseline: 1.4944x; 1.0926x over previous
#include <cuda_runtime.h>
#include <cuda_fp16.h>
#include <math.h>
#include <stdint.h>

// ---------------- scratch (device globals: allocation-free contract) ----------------
__device__ __half g_h1[256 * 400 * 256];            // conv1 out [b][y][x][ci] fp16
__device__ __half g_w1t[256 * 96];                  // conv1 W   [co][k(81 pad 96)] fp16
__device__ __half g_wt[256 * 20736];                // conv2 W   [co][ky*9+kx][ci] fp16
__device__ float g_h2[256 * 9216];                  // conv2 out partial K-half 0 [b][pos][co]
__device__ float g_h2b[256 * 9216];                 // conv2 out partial K-half 1
__device__ float g_u[256 * 9216];                   // squashed  [b][co*36+pos]
__device__ __half g_uhat[(size_t)256 * 1152 * 160]; // u_hat     [b][i][o][d] fp16
__device__ float g_s0p[256 * 8 * 160];              // pass-0 partial sums
__device__ float g_masked[256 * 160];
__device__ float g_d1[256 * 512];
__device__ float g_d2[256 * 1024];

__device__ __forceinline__ void mma_f16(float* c, const uint32_t* a, const uint32_t* b) {
    asm volatile(
        "mma.sync.aligned.m16n8k16.row.col.f32.f16.f16.f32 "
        "{%0,%1,%2,%3}, {%4,%5,%6,%7}, {%8,%9}, {%0,%1,%2,%3};"
        : "+f"(c[0]), "+f"(c[1]), "+f"(c[2]), "+f"(c[3])
        : "r"(a[0]), "r"(a[1]), "r"(a[2]), "r"(a[3]), "r"(b[0]), "r"(b[1]));
}
__device__ __forceinline__ void ldsm4(uint32_t* r, uint32_t addr) {
    asm volatile("ldmatrix.sync.aligned.m8n8.x4.shared.b16 {%0,%1,%2,%3}, [%4];"
        : "=r"(r[0]), "=r"(r[1]), "=r"(r[2]), "=r"(r[3]) : "r"(addr));
}
__device__ __forceinline__ void cp16(uint32_t smem_dst, const void* gsrc) {
    asm volatile("cp.async.cg.shared.global [%0], [%1], 16;" :: "r"(smem_dst), "l"(gsrc));
}
#define CP_COMMIT() asm volatile("cp.async.commit_group;")
#define CP_WAIT2()  asm volatile("cp.async.wait_group 2;")

// ---------------- conv1 weight prep: [co][81] fp32 -> [co][96] fp16 (zero pad) ----------------
__global__ void w1trans_kernel(const float* __restrict__ w1) {
    int co = blockIdx.x;
    int t = threadIdx.x;  // 96
    g_w1t[co * 96 + t] = (t < 81) ? __float2half_rn(w1[co * 81 + t]) : __half(0);
}

// ---------------- conv1 as fp16 mma implicit-im2col GEMM ----------------
// D[n=(b,pos)(128)][co(128)] = X[n][k] * W1t[k][co]; K=96 (81 real). grid (800, 2).
#define XLD 104                      // halfs per smem row (96 + 8 pad) = 208B
#define C1_SMEM (2 * 13312 * 2 + 1568 * 4 + 512)   // Xs + Ws + xf + rbase = 60032B

__global__ __launch_bounds__(256) void conv1_mma(
    const float* __restrict__ x, const float* __restrict__ bias) {
    extern __shared__ __half sm1[];
    __half* Xs = sm1;                     // [128][XLD]
    __half* Ws = sm1 + 13312;             // [128][XLD]
    float* xf = (float*)(sm1 + 26624);    // [2][784]
    int* rbase = (int*)(xf + 1568);       // [128]

    int t = threadIdx.x, bx = blockIdx.x, by = blockIdx.y;
    int lane = t & 31, wid = t >> 5, g = lane >> 2, tg = lane & 3;
    int warp_m = wid >> 2, warp_n = wid & 3;

    int n0 = bx * 128;
    int b0 = n0 / 400;
    int nb = ((n0 + 127) / 400 == b0) ? 1 : 2;

    for (int i = t; i < nb * 784; i += 256) xf[i] = x[b0 * 784 + i];
    if (t < 128) {
        int n = n0 + t;
        int b = n / 400, pos = n - b * 400;
        int oy = pos / 20, ox = pos - oy * 20;
        rbase[t] = (b - b0) * 784 + oy * 28 + ox;
    }
    // W tile: 128 co rows x 96 halfs (12 x uint4 per row)
    const uint4* wsrc = (const uint4*)(g_w1t + (size_t)(by * 128) * 96);
    for (int i = t; i < 128 * 12; i += 256) {
        int r = i / 12, c = i - r * 12;
        *(uint4*)&Ws[r * XLD + c * 8] = wsrc[r * 12 + c];
    }
    __syncthreads();

    // im2col gather X tile (zeros for k in [81,96))
    for (int e = t; e < 128 * 96; e += 256) {
        int row = e / 96, k = e - row * 96;
        float v = 0.f;
        if (k < 81) {
            int ky = k / 9, kx = k - ky * 9;
            v = xf[rbase[row] + ky * 28 + kx];
        }
        Xs[row * XLD + k] = __float2half_rn(v);
    }
    __syncthreads();

    float acc[4][4][4];
#pragma unroll
    for (int mi = 0; mi < 4; mi++)
#pragma unroll
        for (int ni = 0; ni < 4; ni++)
#pragma unroll
            for (int r = 0; r < 4; r++) acc[mi][ni][r] = 0.f;

    uint32_t a_base = (uint32_t)__cvta_generic_to_shared(Xs) +
        (uint32_t)(((warp_m * 64 + (lane & 15)) * XLD + (lane >> 4) * 8) * 2);
    uint32_t b_base = (uint32_t)__cvta_generic_to_shared(Ws) +
        (uint32_t)(((warp_n * 32 + (lane >> 4) * 8 + (lane & 7)) * XLD + ((lane >> 3) & 1) * 8) * 2);

#pragma unroll
    for (int ks = 0; ks < 6; ks++) {
        uint32_t a_f[4][4], b_f[4][2], r[4];
#pragma unroll
        for (int mi = 0; mi < 4; mi++)
            ldsm4(a_f[mi], a_base + (uint32_t)((mi * 16 * XLD + ks * 16) * 2));
        ldsm4(r, b_base + (uint32_t)((ks * 16) * 2));
        b_f[0][0] = r[0]; b_f[0][1] = r[1]; b_f[1][0] = r[2]; b_f[1][1] = r[3];
        ldsm4(r, b_base + (uint32_t)((16 * XLD + ks * 16) * 2));
        b_f[2][0] = r[0]; b_f[2][1] = r[1]; b_f[3][0] = r[2]; b_f[3][1] = r[3];
#pragma unroll
        for (int mi = 0; mi < 4; mi++)
#pragma unroll
            for (int ni = 0; ni < 4; ni++)
                mma_f16(acc[mi][ni], a_f[mi], b_f[ni]);
    }

    // epilogue: D[n][co] + bias, fp16 channel-last
#pragma unroll
    for (int mi = 0; mi < 4; mi++) {
        int n = n0 + warp_m * 64 + mi * 16 + g;
#pragma unroll
        for (int ni = 0; ni < 4; ni++) {
            int co = by * 128 + warp_n * 32 + ni * 8 + 2 * tg;
            float2 bv = *(const float2*)&bias[co];
            __half2 h0 = __floats2half2_rn(acc[mi][ni][0] + bv.x, acc[mi][ni][1] + bv.y);
            __half2 h1 = __floats2half2_rn(acc[mi][ni][2] + bv.x, acc[mi][ni][3] + bv.y);
            *(__half2*)&g_h1[(size_t)n * 256 + co] = h0;
            *(__half2*)&g_h1[(size_t)(n + 8) * 256 + co] = h1;
        }
    }
}

// ---------------- conv2 weight transpose -> fp16 [co][ky*9+kx][ci] ----------------
__global__ void wtrans_kernel(const float* __restrict__ Wc) {
    extern __shared__ float s[];  // 20736 floats
    int co = blockIdx.x;
    int t = threadIdx.x;
    const float* src = Wc + (size_t)co * 20736;
    for (int idx = t; idx < 20736; idx += 256) s[idx] = src[idx];
    __syncthreads();
    __half* dst = g_wt + (size_t)co * 20736;
    for (int idx = t; idx < 20736; idx += 256) {
        int j = idx >> 8, ci = idx & 255;
        dst[idx] = __float2half_rn(s[ci * 81 + j]);
    }
}

// ---------------- conv2: fp16 mma, 3-stage cp.async, split-K 2, ldmatrix A+B ----------------
#define LDT 72                       // halfs per row (64 + 8 pad); 144B
#define STAGE_H (128 * LDT)
#define SM_DYN (6 * STAGE_H * 2)     // 110592 bytes

__global__ __launch_bounds__(256, 2) void conv2_mma(const float* __restrict__ bias) {
    extern __shared__ __half smemh[];
    __half* Abuf = smemh;                 // [3][128][LDT]  rows = co
    __half* Bbuf = smemh + 3 * STAGE_H;   // [3][128][LDT]  rows = pos
    __shared__ int nOffT[128];
    __shared__ int o2Off[128];

    int t = threadIdx.x;
    int bx = blockIdx.x, by = blockIdx.y, bz = blockIdx.z;
    int wid = t >> 5, lane = t & 31;
    int g = lane >> 2, tg = lane & 3;
    int warp_m = wid >> 2, warp_n = wid & 3;

    const int KXY0 = bz ? 41 : 0;
    const int ITERS = (bz ? 40 : 41) * 4;

    if (t < 128) {
        int n = bx * 128 + t;
        int b = n / 36, pos = n - b * 36;
        int oy = pos / 6, ox = pos - oy * 6;
        nOffT[t] = (b * 400 + oy * 40 + ox * 2) * 256;
        o2Off[t] = (b * 36 + pos) * 256;
    }
    __syncthreads();

    int lrow = t >> 1, lpart = (t & 1) * 32;
    const __half* abase = g_wt + (size_t)(by * 128) * 20736;

    auto issue = [&](int ii) {
        int s = ii % 3;
        int kxy = KXY0 + (ii >> 2), cib = (ii & 3) << 6;
        int ky = kxy / 9, kx = kxy - ky * 9;
        int hoff = (ky * 20 + kx) * 256 + cib;
        __half* As_s = Abuf + s * STAGE_H;
        __half* Bs_s = Bbuf + s * STAGE_H;
        const __half* ga = abase + (size_t)lrow * 20736 + kxy * 256 + cib + lpart;
        const __half* gb = g_h1 + nOffT[lrow] + hoff + lpart;
        uint32_t da = (uint32_t)__cvta_generic_to_shared(As_s + lrow * LDT + lpart);
        uint32_t db = (uint32_t)__cvta_generic_to_shared(Bs_s + lrow * LDT + lpart);
#pragma unroll
        for (int q = 0; q < 4; q++) {
            cp16(da + q * 16, ga + q * 8);
            cp16(db + q * 16, gb + q * 8);
        }
        CP_COMMIT();
    };

    issue(0); issue(1); issue(2);

    uint32_t a_base = (uint32_t)__cvta_generic_to_shared(Abuf) +
        (uint32_t)(((warp_m * 64 + (lane & 15)) * LDT + (lane >> 4) * 8) * 2);
    uint32_t b_base = (uint32_t)__cvta_generic_to_shared(Bbuf) +
        (uint32_t)(((warp_n * 32 + (lane >> 4) * 8 + (lane & 7)) * LDT + ((lane >> 3) & 1) * 8) * 2);

    float acc[4][4][4];
#pragma unroll
    for (int mi = 0; mi < 4; mi++)
#pragma unroll
        for (int ni = 0; ni < 4; ni++)
#pragma unroll
            for (int r = 0; r < 4; r++) acc[mi][ni][r] = 0.f;

    for (int i = 0; i < ITERS; i++) {
        CP_WAIT2();
        __syncthreads();

        uint32_t aS = a_base + (uint32_t)((i % 3) * (STAGE_H * 2));
        uint32_t bS = b_base + (uint32_t)((i % 3) * (STAGE_H * 2));

#pragma unroll
        for (int ks = 0; ks < 4; ks++) {
            uint32_t a_f[4][4], b_f[4][2], r[4];
#pragma unroll
            for (int mi = 0; mi < 4; mi++)
                ldsm4(a_f[mi], aS + (uint32_t)((mi * 16 * LDT + ks * 16) * 2));
            ldsm4(r, bS + (uint32_t)((ks * 16) * 2));
            b_f[0][0] = r[0]; b_f[0][1] = r[1]; b_f[1][0] = r[2]; b_f[1][1] = r[3];
            ldsm4(r, bS + (uint32_t)((16 * LDT + ks * 16) * 2));
            b_f[2][0] = r[0]; b_f[2][1] = r[1]; b_f[3][0] = r[2]; b_f[3][1] = r[3];
#pragma unroll
            for (int mi = 0; mi < 4; mi++)
#pragma unroll
                for (int ni = 0; ni < 4; ni++)
                    mma_f16(acc[mi][ni], a_f[mi], b_f[ni]);
        }
        __syncthreads();

        if (i + 3 < ITERS) issue(i + 3);
        else CP_COMMIT();
    }

    float* outb = bz ? g_h2b : g_h2;
#pragma unroll
    for (int mi = 0; mi < 4; mi++) {
        int m0 = warp_m * 64 + mi * 16 + g;
        int mg0 = by * 128 + m0;
        float bv0 = bz ? 0.f : bias[mg0];
        float bv1 = bz ? 0.f : bias[mg0 + 8];
#pragma unroll
        for (int ni = 0; ni < 4; ni++) {
            int n0 = warp_n * 32 + ni * 8 + 2 * tg;
            int o0 = o2Off[n0], o1 = o2Off[n0 + 1];
            outb[o0 + mg0]     = acc[mi][ni][0] + bv0;
            outb[o1 + mg0]     = acc[mi][ni][1] + bv0;
            outb[o0 + mg0 + 8] = acc[mi][ni][2] + bv1;
            outb[o1 + mg0 + 8] = acc[mi][ni][3] + bv1;
        }
    }
}

// ---------------- squash over last spatial axis (sums the two K-halves) ----------------
__global__ void squash_conv_kernel() {
    int gid = blockIdx.x * blockDim.x + threadIdx.x;  // 393216
    int b = gid / 1536;
    int rem = gid - b * 1536;
    int oy = rem >> 8;
    int co = rem & 255;
    float v[6];
    float n2 = 0.f;
#pragma unroll
    for (int j = 0; j < 6; j++) {
        size_t idx = (size_t)(b * 36 + oy * 6 + j) * 256 + co;
        v[j] = g_h2[idx] + g_h2b[idx];
        n2 += v[j] * v[j];
    }
    float nrm = sqrtf(n2);
    float sc = (n2 / (1.f + n2)) / (nrm + 1e-7f);
    float* q = g_u + (size_t)b * 9216 + co * 36 + oy * 6;
#pragma unroll
    for (int j = 0; j < 6; j++) q[j] = v[j] * sc;
}

// ---------------- u_hat (fp16 out): block = input capsule i ----------------
__global__ __launch_bounds__(320) void uhat_kernel2(const float* __restrict__ Wc) {
    __shared__ float u_s[2048];
    int i = blockIdx.x;
    int t = threadIdx.x;
    int b2 = t / 40;
    int od4 = t - b2 * 40;

    for (int idx = t; idx < 2048; idx += 320) {
        int b = idx >> 3, e = idx & 7;
        u_s[idx] = g_u[(size_t)b * 9216 + i * 8 + e];
    }
    int od0 = od4 * 4;
    int o = od0 >> 4;
    int d0 = od0 & 15;
    const float* wp = Wc + ((size_t)(o * 1152 + i) * 16 + d0) * 8;
    float w[4][8];
#pragma unroll
    for (int q = 0; q < 4; q++) {
        float4 w0 = *(const float4*)(wp + q * 8);
        float4 w1 = *(const float4*)(wp + q * 8 + 4);
        w[q][0] = w0.x; w[q][1] = w0.y; w[q][2] = w0.z; w[q][3] = w0.w;
        w[q][4] = w1.x; w[q][5] = w1.y; w[q][6] = w1.z; w[q][7] = w1.w;
    }
    __syncthreads();
    for (int bo = 0; bo < 32; bo++) {
        int b = bo * 8 + b2;
        float ue[8];
#pragma unroll
        for (int e = 0; e < 8; e++) ue[e] = u_s[b * 8 + e];
        float acc[4];
#pragma unroll
        for (int q = 0; q < 4; q++) {
            float a = 0.f;
#pragma unroll
            for (int e = 0; e < 8; e++) a += w[q][e] * ue[e];
            acc[q] = a;
        }
        __half2 h0 = __floats2half2_rn(acc[0], acc[1]);
        __half2 h1 = __floats2half2_rn(acc[2], acc[3]);
        __half2* dst = (__half2*)(g_uhat + ((size_t)b * 1152 + i) * 160 + od0);
        dst[0] = h0; dst[1] = h1;
    }
}

// ---------------- pass-0 partial sums ----------------
__global__ __launch_bounds__(160) void uhat_sum_kernel() {
    int b = blockIdx.x, c = blockIdx.y;
    int t = threadIdx.x;
    const __half* p = g_uhat + ((size_t)b * 1152 + c * 144) * 160 + t;
    float acc = 0.f;
#pragma unroll 4
    for (int i = 0; i < 144; i++) acc += __half2float(p[(size_t)i * 160]);
    g_s0p[(b * 8 + c) * 160 + t] = acc;
}

// ---------------- dynamic routing (passes 1,2; pass 0 from partials), 512 threads ----------------
__device__ __forceinline__ void route_accum(
    const float uh[5], const float* v0s, const float* v1s,
    int p, int lane, float sacc[5]) {
    float c[5];
    float lg[5];
#pragma unroll
    for (int og = 0; og < 5; og++) {
        float tsum = uh[og] * v0s[og * 32 + lane];
        if (p == 2) tsum += uh[og] * v1s[og * 32 + lane];
        tsum += __shfl_xor_sync(0xffffffffu, tsum, 8);
        tsum += __shfl_xor_sync(0xffffffffu, tsum, 4);
        tsum += __shfl_xor_sync(0xffffffffu, tsum, 2);
        tsum += __shfl_xor_sync(0xffffffffu, tsum, 1);
        lg[og] = tsum;
    }
    float m = lg[0];
#pragma unroll
    for (int og = 1; og < 5; og++) m = fmaxf(m, lg[og]);
    m = fmaxf(m, __shfl_xor_sync(0xffffffffu, m, 16));
    float ssum = 0.f;
#pragma unroll
    for (int og = 0; og < 5; og++) { c[og] = expf(lg[og] - m); ssum += c[og]; }
    ssum += __shfl_xor_sync(0xffffffffu, ssum, 16);
    float inv = 1.f / ssum;
#pragma unroll
    for (int og = 0; og < 5; og++) sacc[og] += (c[og] * inv) * uh[og];
}

__global__ __launch_bounds__(512) void routing_kernel(float* __restrict__ out_len) {
    int b = blockIdx.x;
    int tid = threadIdx.x;
    int lane = tid & 31, warp = tid >> 5;   // 16 warps

    __shared__ float v0s[160], v1s[160], v2s[160];
    __shared__ float spart[16 * 160];
    __shared__ float sred[160];
    __shared__ float scale_s[10], len_s[10];
    __shared__ int amax_s;

    const __half* base = g_uhat + (size_t)b * 184320;

    if (tid < 160) {
        float tot = 0.f;
#pragma unroll
        for (int c = 0; c < 8; c++) tot += g_s0p[(b * 8 + c) * 160 + tid];
        sred[tid] = 0.1f * tot;
    }
    __syncthreads();
    if (tid < 10) {
        float n2 = 0.f;
#pragma unroll
        for (int d = 0; d < 16; d++) { float xv = sred[tid * 16 + d]; n2 += xv * xv; }
        float nrm = sqrtf(n2);
        scale_s[tid] = (n2 / (1.f + n2)) / (nrm + 1e-7f);
    }
    __syncthreads();
    if (tid < 160) v0s[tid] = sred[tid] * scale_s[tid >> 4];
    __syncthreads();

    for (int p = 1; p < 3; p++) {
        float sacc[5] = {0.f, 0.f, 0.f, 0.f, 0.f};
        for (int ii = warp; ii < 1152; ii += 32) {
            const __half* pA = base + ii * 160;
            const __half* pB = base + (ii + 16) * 160;
            float uhA[5], uhB[5];
#pragma unroll
            for (int og = 0; og < 5; og++) uhA[og] = __half2float(pA[og * 32 + lane]);
#pragma unroll
            for (int og = 0; og < 5; og++) uhB[og] = __half2float(pB[og * 32 + lane]);
            route_accum(uhA, v0s, v1s, p, lane, sacc);
            route_accum(uhB, v0s, v1s, p, lane, sacc);
        }
#pragma unroll
        for (int og = 0; og < 5; og++) spart[warp * 160 + og * 32 + lane] = sacc[og];
        __syncthreads();
        if (tid < 160) {
            float tot = 0.f;
#pragma unroll
            for (int w = 0; w < 16; w++) tot += spart[w * 160 + tid];
            sred[tid] = tot;
        }
        __syncthreads();
        if (tid < 10) {
            float n2 = 0.f;
#pragma unroll
            for (int d = 0; d < 16; d++) { float xv = sred[tid * 16 + d]; n2 += xv * xv; }
            float nrm = sqrtf(n2);
            scale_s[tid] = (n2 / (1.f + n2)) / (nrm + 1e-7f);
            if (p == 2) len_s[tid] = (n2 / (1.f + n2)) * (nrm / (nrm + 1e-7f));
        }
        __syncthreads();
        float* vdst = (p == 1) ? v1s : v2s;
        if (tid < 160) vdst[tid] = sred[tid] * scale_s[tid >> 4];
        __syncthreads();
    }

    if (tid == 0) {
        int bi = 0;
        float best = len_s[0];
#pragma unroll
        for (int o = 1; o < 10; o++)
            if (len_s[o] > best) { best = len_s[o]; bi = o; }
        amax_s = bi;
    }
    if (tid < 10) out_len[b * 10 + tid] = len_s[tid];
    __syncthreads();
    if (tid < 160) g_masked[b * 160 + tid] = ((tid >> 4) == amax_s) ? v2s[tid] : 0.f;
}

// ---------------- decoder GEMM (64x64x16 tile, 4x4 micro), epilogue fused ----------------
template <int EPI>
__global__ __launch_bounds__(256) void gemm_epi(
    const float* __restrict__ A, const float* __restrict__ W,
    const float* __restrict__ bias, float* __restrict__ C,
    int M, int N, int K) {
    __shared__ float As[16][64];
    __shared__ float Bs[16][64];
    int t = threadIdx.x;
    int bx = blockIdx.x, by = blockIdx.y;
    int arow = t >> 2, ak = (t & 3) * 4;
    int bkr = t >> 4, bnc = (t & 15) * 4;
    int tx = t & 15, ty = t >> 4;

    float acc[4][4];
#pragma unroll
    for (int i = 0; i < 4; i++)
#pragma unroll
        for (int j = 0; j < 4; j++) acc[i][j] = 0.f;

    for (int kk = 0; kk < K; kk += 16) {
        float4 av = *(const float4*)(A + (size_t)(by * 64 + arow) * K + kk + ak);
        int n0 = bx * 64 + bnc;
        float4 bv = make_float4(0.f, 0.f, 0.f, 0.f);
        if (n0 < N) bv = *(const float4*)(W + (size_t)(kk + bkr) * N + n0);
        As[ak + 0][arow] = av.x; As[ak + 1][arow] = av.y;
        As[ak + 2][arow] = av.z; As[ak + 3][arow] = av.w;
        *(float4*)&Bs[bkr][bnc] = bv;
        __syncthreads();
#pragma unroll
        for (int kr = 0; kr < 16; kr++) {
            float af[4], bf[4];
            *(float4*)af = *(const float4*)&As[kr][ty * 4];
            *(float4*)bf = *(const float4*)&Bs[kr][tx * 4];
#pragma unroll
            for (int mi = 0; mi < 4; mi++)
#pragma unroll
                for (int ni = 0; ni < 4; ni++) acc[mi][ni] += af[mi] * bf[ni];
        }
        __syncthreads();
    }

#pragma unroll
    for (int mi = 0; mi < 4; mi++) {
        int m = by * 64 + ty * 4 + mi;
#pragma unroll
        for (int ni = 0; ni < 4; ni++) {
            int n = bx * 64 + tx * 4 + ni;
            if (n < N) {
                float v = acc[mi][ni] + bias[n];
                if (EPI == 1) v = fmaxf(v, 0.f);
                if (EPI == 2) v = 1.f / (1.f + expf(-v));
                C[(size_t)m * N + n] = v;
            }
        }
    }
}

// ---------------- launch ----------------
extern "C" void kernel_launch(void* const* d_in, const int* in_sizes, int n_in,
                              void* d_out, int out_size) {
    const float* x     = (const float*)d_in[0];
    const float* c1w   = (const float*)d_in[1];
    const float* c1b   = (const float*)d_in[2];
    const float* c2w   = (const float*)d_in[3];
    const float* c2b   = (const float*)d_in[4];
    const float* Wcaps = (const float*)d_in[5];
    const float* dw1   = (const float*)d_in[6];
    const float* db1   = (const float*)d_in[7];
    const float* dw2   = (const float*)d_in[8];
    const float* db2   = (const float*)d_in[9];
    const float* dw3   = (const float*)d_in[10];
    const float* db3   = (const float*)d_in[11];
    float* out = (float*)d_out;

    float* g_d1_ptr; cudaGetSymbolAddress((void**)&g_d1_ptr, g_d1);
    float* g_d2_ptr; cudaGetSymbolAddress((void**)&g_d2_ptr, g_d2);
    float* g_m_ptr;  cudaGetSymbolAddress((void**)&g_m_ptr, g_masked);

    cudaFuncSetAttribute(wtrans_kernel, cudaFuncAttributeMaxDynamicSharedMemorySize,
                         20736 * 4);
    cudaFuncSetAttribute(conv2_mma, cudaFuncAttributeMaxDynamicSharedMemorySize, SM_DYN);
    cudaFuncSetAttribute(conv1_mma, cudaFuncAttributeMaxDynamicSharedMemorySize, C1_SMEM);

    w1trans_kernel<<<256, 96>>>(c1w);
    wtrans_kernel<<<256, 256, 20736 * 4>>>(c2w);
    conv1_mma<<<dim3(800, 2), 256, C1_SMEM>>>(x, c1b);
    conv2_mma<<<dim3(72, 2, 2), 256, SM_DYN>>>(c2b);
    squash_conv_kernel<<<1536, 256>>>();
    uhat_kernel2<<<1152, 320>>>(Wcaps);
    uhat_sum_kernel<<<dim3(256, 8), 160>>>();
    routing_kernel<<<256, 512>>>(out);
    gemm_epi<1><<<dim3(8, 4), 256>>>(g_m_ptr, dw1, db1, g_d1_ptr, 256, 512, 160);
    gemm_epi<1><<<dim3(16, 4), 256>>>(g_d1_ptr, dw2, db2, g_d2_ptr, 256, 1024, 512);
    gemm_epi<2><<<dim3(13, 4), 256>>>(g_d2_ptr, dw3, db3, out + 2560, 256, 784, 1024);
}